// round 2
// baseline (speedup 1.0000x reference)
#include <cuda_runtime.h>

#define F_ 48
#define G_ 4
#define C_ 128
#define GF 192
#define NPIX 64
#define THREADS 512
#define WFS 193            // padded Wf row stride (193 % 32 == 1 -> conflict-free)
#define SCALE_C 0.999f

// shared memory layout (floats)
#define OFF_WF   0
#define OFF_X    (OFF_WF + C_*WFS)            // 24704
#define OFF_BUF  (OFF_X + C_*NPIX)            // +8192
#define OFF_QE   (OFF_BUF + GF*NPIX)          // +12288
#define OFF_QM   (OFF_QE + F_*16)
#define OFF_ITS  (OFF_QM + F_*16)
#define OFF_ISC  (OFF_ITS + F_)
#define OFF_LSC  (OFF_ISC + F_)
#define SMEM_FLOATS (OFF_LSC + F_)
#define SMEM_BYTES (SMEM_FLOATS * 4)

struct Precomp {
    float Qeff[F_][G_][G_];   // Q / sigma_max^2, [f][l][g]
    float Qm[F_][G_][G_];     // normalized Q,    [f][l][g]
    float its[F_];            // SCALE / taus[f]
    float invsc[2][F_];       // 1 / scaling[b][f]
    float lscal[2][F_];       // lamb_e * scaling[b][f]
    float eps_e;
    float inv_denom;          // 1/(1 + lamb_e*(1+eps_e))
};
__device__ Precomp g_pre;

// ---------------- packed f32x2 helpers (sm_103a) ----------------
__device__ __forceinline__ unsigned long long pack2(float a, float b) {
    unsigned long long r;
    asm("mov.b64 %0,{%1,%2};" : "=l"(r) : "f"(a), "f"(b));
    return r;
}
__device__ __forceinline__ void fma2(unsigned long long& d,
                                     unsigned long long a,
                                     unsigned long long b) {
    asm("fma.rn.f32x2 %0,%1,%2,%0;" : "+l"(d) : "l"(a), "l"(b));
}
__device__ __forceinline__ float2 unpack2(unsigned long long v) {
    float2 r;
    asm("mov.b64 {%0,%1},%2;" : "=f"(r.x), "=f"(r.y) : "l"(v));
    return r;
}

// ---------------- l1-ball projection for a 4-vector ----------------
__device__ __forceinline__ void proj4(float x0, float x1, float x2, float x3,
                                      float& o0, float& o1, float& o2, float& o3) {
    float a0 = fabsf(x0), a1 = fabsf(x1), a2 = fabsf(x2), a3 = fabsf(x3);
    float ssum = a0 + a1 + a2 + a3;
    // sorting network (descending): 5 comparators
    float m01 = fmaxf(a0, a1), n01 = fminf(a0, a1);
    float m23 = fmaxf(a2, a3), n23 = fminf(a2, a3);
    float s0 = fmaxf(m01, m23), lo0 = fminf(m01, m23);
    float hi1 = fmaxf(n01, n23), s3 = fminf(n01, n23);
    float s1 = fmaxf(lo0, hi1), s2 = fminf(lo0, hi1);
    float c1 = s0 - 1.f;
    float c2 = c1 + s1;
    float c3 = c2 + s2;
    float c4 = c3 + s3;
    int rho = 1 + (s1 * 2.f > c2) + (s2 * 3.f > c3) + (s3 * 4.f > c4);
    float num = (rho == 1) ? c1 : (rho == 2) ? c2 : (rho == 3) ? c3 : c4;
    float theta = fmaxf(num / (float)rho, 0.f);
    theta = (ssum <= 1.f) ? 0.f : theta;
    o0 = copysignf(fmaxf(a0 - theta, 0.f), x0);
    o1 = copysignf(fmaxf(a1 - theta, 0.f), x1);
    o2 = copysignf(fmaxf(a2 - theta, 0.f), x2);
    o3 = copysignf(fmaxf(a3 - theta, 0.f), x3);
}

// ---------------- precompute kernel ----------------
__global__ void precomp_kernel(const float* __restrict__ sigma,
                               const float* __restrict__ Qp,
                               const float* __restrict__ tausp,
                               const float* __restrict__ lambp,
                               const float* __restrict__ epsp,
                               const float* __restrict__ w1, const float* __restrict__ b1,
                               const float* __restrict__ w2, const float* __restrict__ b2,
                               const float* __restrict__ w3, const float* __restrict__ b3) {
    __shared__ float h1[2][F_], h2[2][F_];
    int t = threadIdx.x;
    float lamb_e = expf(lambp[0]);
    float eps_e = expf(epsp[0]);
    if (t == 0) {
        g_pre.eps_e = eps_e;
        g_pre.inv_denom = 1.f / (1.f + lamb_e * (1.f + eps_e));
    }
    if (t < F_) {
        // normalize Q rows by l1 sum (axis=2), clamp >= 1
        float Qm[G_][G_];
#pragma unroll
        for (int l = 0; l < 4; l++) {
            float rs = 0.f;
#pragma unroll
            for (int g = 0; g < 4; g++) rs += fabsf(Qp[t * 16 + l * 4 + g]);
            float inv = 1.f / fmaxf(rs, 1.f);
#pragma unroll
            for (int g = 0; g < 4; g++) Qm[l][g] = Qp[t * 16 + l * 4 + g] * inv;
        }
        // S = Q^T Q (symmetric 4x4); largest eigenvalue via cyclic Jacobi
        double S[4][4];
        for (int i = 0; i < 4; i++)
            for (int j = 0; j < 4; j++) {
                double acc = 0.0;
                for (int l = 0; l < 4; l++) acc += (double)Qm[l][i] * (double)Qm[l][j];
                S[i][j] = acc;
            }
        const int JP[6] = {0, 0, 0, 1, 1, 2};
        const int JQ[6] = {1, 2, 3, 2, 3, 3};
        for (int sw = 0; sw < 25; sw++) {
            for (int r = 0; r < 6; r++) {
                int p = JP[r], q = JQ[r];
                double apq = S[p][q];
                if (fabs(apq) < 1e-30) continue;
                double th = (S[q][q] - S[p][p]) / (2.0 * apq);
                double tt = (th >= 0.0 ? 1.0 : -1.0) / (fabs(th) + sqrt(1.0 + th * th));
                double cc = 1.0 / sqrt(1.0 + tt * tt), ss = tt * cc;
                for (int k = 0; k < 4; k++) {
                    double skp = S[k][p], skq = S[k][q];
                    S[k][p] = cc * skp - ss * skq;
                    S[k][q] = ss * skp + cc * skq;
                }
                for (int k = 0; k < 4; k++) {
                    double spk = S[p][k], sqk = S[q][k];
                    S[p][k] = cc * spk - ss * sqk;
                    S[q][k] = ss * spk + cc * sqk;
                }
            }
        }
        double lam = S[0][0];
        for (int i = 1; i < 4; i++) lam = (S[i][i] > lam) ? S[i][i] : lam;
        float inv_lam = (float)(1.0 / lam);   // = 1 / Q_norms^2
#pragma unroll
        for (int l = 0; l < 4; l++)
#pragma unroll
            for (int g = 0; g < 4; g++) {
                g_pre.Qm[t][l][g] = Qm[l][g];
                g_pre.Qeff[t][l][g] = Qm[l][g] * inv_lam;
            }
        g_pre.its[t] = SCALE_C / expf(fmaxf(tausp[t], 0.f));
        for (int bb = 0; bb < 2; bb++)
            h1[bb][t] = fmaxf(fmaf(sigma[bb] * 20.f - 2.f, w1[t], b1[t]), 0.f);
    }
    __syncthreads();
    if (t < F_) {
        for (int bb = 0; bb < 2; bb++) {
            float a = b2[t];
            for (int j = 0; j < F_; j++) a += h1[bb][j] * w2[j * F_ + t];
            h2[bb][t] = fmaxf(a, 0.f);
        }
    }
    __syncthreads();
    if (t < F_) {
        for (int bb = 0; bb < 2; bb++) {
            float a = b3[t];
            for (int j = 0; j < F_; j++) a += h2[bb][j] * w3[j * F_ + t];
            float sc = fmaxf(fmaf(a, 0.05f, sigma[bb]), 0.f) + 1e-9f; // SLOPE = 1
            g_pre.invsc[bb][t] = 1.f / sc;
            g_pre.lscal[bb][t] = lamb_e * sc;
        }
    }
}

// ---------------- fused main kernel (512 threads / CTA) ----------------
__global__ void __launch_bounds__(THREADS, 1)
mfoe_kernel(const float* __restrict__ xn, const float* __restrict__ Wf,
            const int* __restrict__ niter_p, float* __restrict__ out) {
    extern __shared__ float sm[];
    float* Wf_s = sm + OFF_WF;   // [c][gf], stride 193
    float* x_s  = sm + OFF_X;    // [c][px], stride 64
    float* buf  = sm + OFF_BUF;  // [gf][px], stride 64
    float* Qe_s = sm + OFF_QE;
    float* Qm_s = sm + OFF_QM;
    float* ITS  = sm + OFF_ITS;
    float* ISC  = sm + OFF_ISC;
    float* LSC  = sm + OFF_LSC;

    const int t = threadIdx.x;
    const int pix0 = blockIdx.x * NPIX;
    const int b = pix0 >> 14;              // 16384 spatial positions per batch
    const int sp0 = pix0 & 16383;
    const float* xnb = xn + (size_t)b * (C_ * 16384) + sp0;
    float* outb = out + (size_t)b * (C_ * 16384) + sp0;

    // load Wf into shared: global [gf][c] -> shared [c][gf]
    for (int i = t; i < GF * C_; i += THREADS) {
        int gf = i >> 7, c = i & 127;
        Wf_s[c * WFS + gf] = Wf[i];
    }
    // per-f constants
    {
        const float* qe = (const float*)g_pre.Qeff;
        const float* qm = (const float*)g_pre.Qm;
        for (int i = t; i < F_ * 16; i += THREADS) {
            Qe_s[i] = qe[i];
            Qm_s[i] = qm[i];
        }
        if (t < F_) {
            ITS[t] = g_pre.its[t];
            ISC[t] = g_pre.invsc[b][t];
            LSC[t] = g_pre.lscal[b][t];
        }
    }
    // init x = x_noisy
    for (int i = t; i < C_ * NPIX; i += THREADS) {
        int c = i >> 6, p = i & 63;
        x_s[i] = xnb[c * 16384 + p];
    }
    const float eps_e = g_pre.eps_e;
    const float inv_denom = g_pre.inv_denom;
    const int niter = *niter_p;
    __syncthreads();

    const int pxg = t & 7;                 // pixel group
    const int px0 = pxg << 3;              // 8 pixels per thread
    const int grp = t >> 3;                // 0..63
    const int gf0 = grp * 3;               // forward: 3 gf rows
    const int cg  = grp;                   // backward: c = cg, cg+64
    const int fb  = t >> 6;                // activation: f base 0..7
    const int pxa = t & 63;                // activation: pixel

    for (int it = 0; it < niter; ++it) {
        // ---------- forward: Lx[gf][px] = sum_c Wf[gf][c] * x[c][px] ----------
        {
            unsigned long long acc[3][4];
#pragma unroll
            for (int k = 0; k < 3; k++)
#pragma unroll
                for (int j = 0; j < 4; j++) acc[k][j] = 0ull;

            const float* xcol = x_s + px0;
            const float* wrow0 = Wf_s + gf0;
#pragma unroll 4
            for (int c = 0; c < C_; c++) {
                ulonglong2 xv0 = *(const ulonglong2*)(xcol + c * 64);
                ulonglong2 xv1 = *(const ulonglong2*)(xcol + c * 64 + 4);
                const float* wr = wrow0 + c * WFS;
#pragma unroll
                for (int k = 0; k < 3; k++) {
                    unsigned long long wp = pack2(wr[k], wr[k]);
                    fma2(acc[k][0], wp, xv0.x);
                    fma2(acc[k][1], wp, xv0.y);
                    fma2(acc[k][2], wp, xv1.x);
                    fma2(acc[k][3], wp, xv1.y);
                }
            }
#pragma unroll
            for (int k = 0; k < 3; k++) {
                ulonglong2* dst = (ulonglong2*)(buf + (gf0 + k) * 64 + px0);
                dst[0] = make_ulonglong2(acc[k][0], acc[k][1]);
                dst[1] = make_ulonglong2(acc[k][2], acc[k][3]);
            }
        }
        __syncthreads();

        // ---------- activation (per f, per pixel), in place in buf ----------
#pragma unroll 1
        for (int i = 0; i < 6; i++) {
            int f = i * 8 + fb;
            float isc = ISC[f];
            float xv0 = buf[(0 * F_ + f) * 64 + pxa] * isc;
            float xv1 = buf[(1 * F_ + f) * 64 + pxa] * isc;
            float xv2 = buf[(2 * F_ + f) * 64 + pxa] * isc;
            float xv3 = buf[(3 * F_ + f) * 64 + pxa] * isc;

            float gc0, gc1, gc2, gc3;
            proj4(xv0, xv1, xv2, xv3, gc0, gc1, gc2, gc3);
            gc0 = fmaf(eps_e, xv0, gc0);
            gc1 = fmaf(eps_e, xv1, gc1);
            gc2 = fmaf(eps_e, xv2, gc2);
            gc3 = fmaf(eps_e, xv3, gc3);

            float its = ITS[f];
            const float* qe = Qe_s + f * 16;   // [l][g]
            float y0 = its * (qe[0] * xv0 + qe[1] * xv1 + qe[2] * xv2 + qe[3] * xv3);
            float y1 = its * (qe[4] * xv0 + qe[5] * xv1 + qe[6] * xv2 + qe[7] * xv3);
            float y2 = its * (qe[8] * xv0 + qe[9] * xv1 + qe[10] * xv2 + qe[11] * xv3);
            float y3 = its * (qe[12] * xv0 + qe[13] * xv1 + qe[14] * xv2 + qe[15] * xv3);

            float gy0, gy1, gy2, gy3;
            proj4(y0, y1, y2, y3, gy0, gy1, gy2, gy3);
            gy0 = fmaf(eps_e, y0, gy0);
            gy1 = fmaf(eps_e, y1, gy1);
            gy2 = fmaf(eps_e, y2, gy2);
            gy3 = fmaf(eps_e, y3, gy3);

            const float* qm = Qm_s + f * 16;   // [g][l] access: qm[g*4 + l]
            float ls = LSC[f];
#pragma unroll
            for (int l = 0; l < 4; l++) {
                float g2 = SCALE_C * (qm[0 * 4 + l] * gy0 + qm[1 * 4 + l] * gy1 +
                                      qm[2 * 4 + l] * gy2 + qm[3 * 4 + l] * gy3);
                float gcl = (l == 0) ? gc0 : (l == 1) ? gc1 : (l == 2) ? gc2 : gc3;
                buf[(l * F_ + f) * 64 + pxa] = ls * (gcl - g2);
            }
        }
        __syncthreads();

        // ---------- backward + update: x[c][px] -= (x - xn + W^T v)/denom ----------
        {
            unsigned long long bac[2][4];
#pragma unroll
            for (int k = 0; k < 2; k++)
#pragma unroll
                for (int j = 0; j < 4; j++) bac[k][j] = 0ull;

            const float* vcol = buf + px0;
#pragma unroll 4
            for (int gf = 0; gf < GF; gf++) {
                ulonglong2 v0 = *(const ulonglong2*)(vcol + gf * 64);
                ulonglong2 v1 = *(const ulonglong2*)(vcol + gf * 64 + 4);
#pragma unroll
                for (int k = 0; k < 2; k++) {
                    float w = Wf_s[(cg + 64 * k) * WFS + gf];
                    unsigned long long wp = pack2(w, w);
                    fma2(bac[k][0], wp, v0.x);
                    fma2(bac[k][1], wp, v0.y);
                    fma2(bac[k][2], wp, v1.x);
                    fma2(bac[k][3], wp, v1.y);
                }
            }
#pragma unroll
            for (int k = 0; k < 2; k++) {
                int c = cg + 64 * k;
                const float* xng = xnb + c * 16384 + px0;
                float4 n0 = *(const float4*)(xng);
                float4 n1 = *(const float4*)(xng + 4);
                float* xr = x_s + c * 64 + px0;
                float4 xo0 = *(float4*)(xr);
                float4 xo1 = *(float4*)(xr + 4);
                float2 a0 = unpack2(bac[k][0]);
                float2 a1 = unpack2(bac[k][1]);
                float2 a2 = unpack2(bac[k][2]);
                float2 a3 = unpack2(bac[k][3]);
                xo0.x = xo0.x - (xo0.x - n0.x + a0.x) * inv_denom;
                xo0.y = xo0.y - (xo0.y - n0.y + a0.y) * inv_denom;
                xo0.z = xo0.z - (xo0.z - n0.z + a1.x) * inv_denom;
                xo0.w = xo0.w - (xo0.w - n0.w + a1.y) * inv_denom;
                xo1.x = xo1.x - (xo1.x - n1.x + a2.x) * inv_denom;
                xo1.y = xo1.y - (xo1.y - n1.y + a2.y) * inv_denom;
                xo1.z = xo1.z - (xo1.z - n1.z + a3.x) * inv_denom;
                xo1.w = xo1.w - (xo1.w - n1.w + a3.y) * inv_denom;
                *(float4*)(xr) = xo0;
                *(float4*)(xr + 4) = xo1;
            }
        }
        __syncthreads();
    }

    // write result
    for (int i = t; i < C_ * NPIX; i += THREADS) {
        int c = i >> 6, p = i & 63;
        outb[c * 16384 + p] = x_s[i];
    }
}

extern "C" void kernel_launch(void* const* d_in, const int* in_sizes, int n_in,
                              void* d_out, int out_size) {
    const float* xn    = (const float*)d_in[0];
    const float* sigma = (const float*)d_in[1];
    const float* Qp    = (const float*)d_in[2];
    const float* tausp = (const float*)d_in[3];
    const float* lamb  = (const float*)d_in[4];
    const float* epso  = (const float*)d_in[5];
    const float* w1    = (const float*)d_in[6];
    const float* b1    = (const float*)d_in[7];
    const float* w2    = (const float*)d_in[8];
    const float* b2    = (const float*)d_in[9];
    const float* w3    = (const float*)d_in[10];
    const float* b3    = (const float*)d_in[11];
    const float* Wf    = (const float*)d_in[12];
    const int* niter   = (const int*)d_in[13];
    float* out = (float*)d_out;

    cudaFuncSetAttribute(mfoe_kernel, cudaFuncAttributeMaxDynamicSharedMemorySize, SMEM_BYTES);
    precomp_kernel<<<1, 64>>>(sigma, Qp, tausp, lamb, epso, w1, b1, w2, b2, w3, b3);
    mfoe_kernel<<<512, THREADS, SMEM_BYTES>>>(xn, Wf, niter, out);
}

// round 3
// speedup vs baseline: 1.6533x; 1.6533x over previous
#include <cuda_runtime.h>

#define F_ 48
#define G_ 4
#define C_ 128
#define GF 192
#define NPIX 64
#define THREADS 256
#define WFS 194            // padded Wf row stride (even -> float2-aligned weight loads)
#define SCALE_C 0.999f

// shared memory layout (floats)
#define OFF_WF   0
#define OFF_X    (OFF_WF + C_*WFS)
#define OFF_BUF  (OFF_X + C_*NPIX)
#define OFF_QE   (OFF_BUF + GF*NPIX)
#define OFF_QM   (OFF_QE + F_*16)
#define OFF_ITS  (OFF_QM + F_*16)
#define OFF_ISC  (OFF_ITS + F_)
#define OFF_LSC  (OFF_ISC + F_)
#define SMEM_FLOATS (OFF_LSC + F_)
#define SMEM_BYTES (SMEM_FLOATS * 4)

struct Precomp {
    float Qeff[F_][G_][G_];
    float Qm[F_][G_][G_];
    float its[F_];
    float invsc[2][F_];
    float lscal[2][F_];
    float eps_e;
    float inv_denom;
};
__device__ Precomp g_pre;

// ---------------- packed f32x2 helpers (sm_103a) ----------------
__device__ __forceinline__ unsigned long long pack2(float a, float b) {
    unsigned long long r;
    asm("mov.b64 %0,{%1,%2};" : "=l"(r) : "f"(a), "f"(b));
    return r;
}
__device__ __forceinline__ void fma2(unsigned long long& d,
                                     unsigned long long a,
                                     unsigned long long b) {
    asm("fma.rn.f32x2 %0,%1,%2,%0;" : "+l"(d) : "l"(a), "l"(b));
}
__device__ __forceinline__ float2 unpack2(unsigned long long v) {
    float2 r;
    asm("mov.b64 {%0,%1},%2;" : "=f"(r.x), "=f"(r.y) : "l"(v));
    return r;
}

// ---------------- l1-ball projection for a 4-vector ----------------
__device__ __forceinline__ void proj4(float x0, float x1, float x2, float x3,
                                      float& o0, float& o1, float& o2, float& o3) {
    float a0 = fabsf(x0), a1 = fabsf(x1), a2 = fabsf(x2), a3 = fabsf(x3);
    float ssum = a0 + a1 + a2 + a3;
    float m01 = fmaxf(a0, a1), n01 = fminf(a0, a1);
    float m23 = fmaxf(a2, a3), n23 = fminf(a2, a3);
    float s0 = fmaxf(m01, m23), lo0 = fminf(m01, m23);
    float hi1 = fmaxf(n01, n23), s3 = fminf(n01, n23);
    float s1 = fmaxf(lo0, hi1), s2 = fminf(lo0, hi1);
    float c1 = s0 - 1.f;
    float c2 = c1 + s1;
    float c3 = c2 + s2;
    float c4 = c3 + s3;
    int rho = 1 + (s1 * 2.f > c2) + (s2 * 3.f > c3) + (s3 * 4.f > c4);
    float num = (rho == 1) ? c1 : (rho == 2) ? c2 : (rho == 3) ? c3 : c4;
    float theta = fmaxf(num / (float)rho, 0.f);
    theta = (ssum <= 1.f) ? 0.f : theta;
    o0 = copysignf(fmaxf(a0 - theta, 0.f), x0);
    o1 = copysignf(fmaxf(a1 - theta, 0.f), x1);
    o2 = copysignf(fmaxf(a2 - theta, 0.f), x2);
    o3 = copysignf(fmaxf(a3 - theta, 0.f), x3);
}

// ---------------- precompute kernel ----------------
__global__ void precomp_kernel(const float* __restrict__ sigma,
                               const float* __restrict__ Qp,
                               const float* __restrict__ tausp,
                               const float* __restrict__ lambp,
                               const float* __restrict__ epsp,
                               const float* __restrict__ w1, const float* __restrict__ b1,
                               const float* __restrict__ w2, const float* __restrict__ b2,
                               const float* __restrict__ w3, const float* __restrict__ b3) {
    __shared__ float h1[2][F_], h2[2][F_];
    int t = threadIdx.x;
    float lamb_e = expf(lambp[0]);
    float eps_e = expf(epsp[0]);
    if (t == 0) {
        g_pre.eps_e = eps_e;
        g_pre.inv_denom = 1.f / (1.f + lamb_e * (1.f + eps_e));
    }
    if (t < F_) {
        float Qm[G_][G_];
#pragma unroll
        for (int l = 0; l < 4; l++) {
            float rs = 0.f;
#pragma unroll
            for (int g = 0; g < 4; g++) rs += fabsf(Qp[t * 16 + l * 4 + g]);
            float inv = 1.f / fmaxf(rs, 1.f);
#pragma unroll
            for (int g = 0; g < 4; g++) Qm[l][g] = Qp[t * 16 + l * 4 + g] * inv;
        }
        double S[4][4];
        for (int i = 0; i < 4; i++)
            for (int j = 0; j < 4; j++) {
                double acc = 0.0;
                for (int l = 0; l < 4; l++) acc += (double)Qm[l][i] * (double)Qm[l][j];
                S[i][j] = acc;
            }
        const int JP[6] = {0, 0, 0, 1, 1, 2};
        const int JQ[6] = {1, 2, 3, 2, 3, 3};
        for (int sw = 0; sw < 25; sw++) {
            for (int r = 0; r < 6; r++) {
                int p = JP[r], q = JQ[r];
                double apq = S[p][q];
                if (fabs(apq) < 1e-30) continue;
                double th = (S[q][q] - S[p][p]) / (2.0 * apq);
                double tt = (th >= 0.0 ? 1.0 : -1.0) / (fabs(th) + sqrt(1.0 + th * th));
                double cc = 1.0 / sqrt(1.0 + tt * tt), ss = tt * cc;
                for (int k = 0; k < 4; k++) {
                    double skp = S[k][p], skq = S[k][q];
                    S[k][p] = cc * skp - ss * skq;
                    S[k][q] = ss * skp + cc * skq;
                }
                for (int k = 0; k < 4; k++) {
                    double spk = S[p][k], sqk = S[q][k];
                    S[p][k] = cc * spk - ss * sqk;
                    S[q][k] = ss * spk + cc * sqk;
                }
            }
        }
        double lam = S[0][0];
        for (int i = 1; i < 4; i++) lam = (S[i][i] > lam) ? S[i][i] : lam;
        float inv_lam = (float)(1.0 / lam);
#pragma unroll
        for (int l = 0; l < 4; l++)
#pragma unroll
            for (int g = 0; g < 4; g++) {
                g_pre.Qm[t][l][g] = Qm[l][g];
                g_pre.Qeff[t][l][g] = Qm[l][g] * inv_lam;
            }
        g_pre.its[t] = SCALE_C / expf(fmaxf(tausp[t], 0.f));
        for (int bb = 0; bb < 2; bb++)
            h1[bb][t] = fmaxf(fmaf(sigma[bb] * 20.f - 2.f, w1[t], b1[t]), 0.f);
    }
    __syncthreads();
    if (t < F_) {
        for (int bb = 0; bb < 2; bb++) {
            float a = b2[t];
            for (int j = 0; j < F_; j++) a += h1[bb][j] * w2[j * F_ + t];
            h2[bb][t] = fmaxf(a, 0.f);
        }
    }
    __syncthreads();
    if (t < F_) {
        for (int bb = 0; bb < 2; bb++) {
            float a = b3[t];
            for (int j = 0; j < F_; j++) a += h2[bb][j] * w3[j * F_ + t];
            float sc = fmaxf(fmaf(a, 0.05f, sigma[bb]), 0.f) + 1e-9f;
            g_pre.invsc[bb][t] = 1.f / sc;
            g_pre.lscal[bb][t] = lamb_e * sc;
        }
    }
}

// ---------------- fused main kernel (256 threads, vectorized weight loads) ----------------
__global__ void __launch_bounds__(THREADS, 1)
mfoe_kernel(const float* __restrict__ xn, const float* __restrict__ Wf,
            const int* __restrict__ niter_p, float* __restrict__ out) {
    extern __shared__ float sm[];
    float* Wf_s = sm + OFF_WF;   // [c][gf], stride 194 (even)
    float* x_s  = sm + OFF_X;    // [c][px], stride 64
    float* buf  = sm + OFF_BUF;  // [gf][px], stride 64
    float* Qe_s = sm + OFF_QE;
    float* Qm_s = sm + OFF_QM;
    float* ITS  = sm + OFF_ITS;
    float* ISC  = sm + OFF_ISC;
    float* LSC  = sm + OFF_LSC;

    const int t = threadIdx.x;
    const int pix0 = blockIdx.x * NPIX;
    const int b = pix0 >> 14;
    const int sp0 = pix0 & 16383;
    const float* xnb = xn + (size_t)b * (C_ * 16384) + sp0;
    float* outb = out + (size_t)b * (C_ * 16384) + sp0;

    for (int i = t; i < GF * C_; i += THREADS) {
        int gf = i >> 7, c = i & 127;
        Wf_s[c * WFS + gf] = Wf[i];
    }
    {
        const float* qe = (const float*)g_pre.Qeff;
        const float* qm = (const float*)g_pre.Qm;
        for (int i = t; i < F_ * 16; i += THREADS) {
            Qe_s[i] = qe[i];
            Qm_s[i] = qm[i];
        }
        if (t < F_) {
            ITS[t] = g_pre.its[t];
            ISC[t] = g_pre.invsc[b][t];
            LSC[t] = g_pre.lscal[b][t];
        }
    }
    for (int i = t; i < C_ * NPIX; i += THREADS) {
        int c = i >> 6, p = i & 63;
        x_s[i] = xnb[c * 16384 + p];
    }
    const float eps_e = g_pre.eps_e;
    const float inv_denom = g_pre.inv_denom;
    const int niter = *niter_p;
    __syncthreads();

    const int pxg = t & 7;                 // pixel group
    const int px0 = pxg << 3;              // 8 pixels per thread
    const int grp = t >> 3;                // 0..31
    const int gf0 = grp * 6;               // forward: 6 gf rows (even -> f2-aligned)
    const int cg  = grp;                   // backward: c = cg + 32*k
    const int fb  = t >> 6;                // activation: f base 0..3
    const int pxa = t & 63;                // activation: pixel

    for (int it = 0; it < niter; ++it) {
        // ---------- forward: Lx[gf][px] = sum_c Wf[gf][c] * x[c][px] ----------
        {
            unsigned long long acc[6][4];
#pragma unroll
            for (int k = 0; k < 6; k++)
#pragma unroll
                for (int j = 0; j < 4; j++) acc[k][j] = 0ull;

            const float* xcol = x_s + px0;
            const float* wrow0 = Wf_s + gf0;
#pragma unroll 2
            for (int c = 0; c < C_; c++) {
                ulonglong2 xv0 = *(const ulonglong2*)(xcol + c * 64);
                ulonglong2 xv1 = *(const ulonglong2*)(xcol + c * 64 + 4);
                const float* wr = wrow0 + c * WFS;
                float2 w01 = *(const float2*)(wr);
                float2 w23 = *(const float2*)(wr + 2);
                float2 w45 = *(const float2*)(wr + 4);
                float wv[6] = {w01.x, w01.y, w23.x, w23.y, w45.x, w45.y};
#pragma unroll
                for (int k = 0; k < 6; k++) {
                    unsigned long long wp = pack2(wv[k], wv[k]);
                    fma2(acc[k][0], wp, xv0.x);
                    fma2(acc[k][1], wp, xv0.y);
                    fma2(acc[k][2], wp, xv1.x);
                    fma2(acc[k][3], wp, xv1.y);
                }
            }
#pragma unroll
            for (int k = 0; k < 6; k++) {
                ulonglong2* dst = (ulonglong2*)(buf + (gf0 + k) * 64 + px0);
                dst[0] = make_ulonglong2(acc[k][0], acc[k][1]);
                dst[1] = make_ulonglong2(acc[k][2], acc[k][3]);
            }
        }
        __syncthreads();

        // ---------- activation (per f, per pixel), in place in buf ----------
#pragma unroll 1
        for (int i = 0; i < 12; i++) {
            int f = i * 4 + fb;
            float isc = ISC[f];
            float xv0 = buf[(0 * F_ + f) * 64 + pxa] * isc;
            float xv1 = buf[(1 * F_ + f) * 64 + pxa] * isc;
            float xv2 = buf[(2 * F_ + f) * 64 + pxa] * isc;
            float xv3 = buf[(3 * F_ + f) * 64 + pxa] * isc;

            float gc0, gc1, gc2, gc3;
            proj4(xv0, xv1, xv2, xv3, gc0, gc1, gc2, gc3);
            gc0 = fmaf(eps_e, xv0, gc0);
            gc1 = fmaf(eps_e, xv1, gc1);
            gc2 = fmaf(eps_e, xv2, gc2);
            gc3 = fmaf(eps_e, xv3, gc3);

            float its = ITS[f];
            const float* qe = Qe_s + f * 16;
            float y0 = its * (qe[0] * xv0 + qe[1] * xv1 + qe[2] * xv2 + qe[3] * xv3);
            float y1 = its * (qe[4] * xv0 + qe[5] * xv1 + qe[6] * xv2 + qe[7] * xv3);
            float y2 = its * (qe[8] * xv0 + qe[9] * xv1 + qe[10] * xv2 + qe[11] * xv3);
            float y3 = its * (qe[12] * xv0 + qe[13] * xv1 + qe[14] * xv2 + qe[15] * xv3);

            float gy0, gy1, gy2, gy3;
            proj4(y0, y1, y2, y3, gy0, gy1, gy2, gy3);
            gy0 = fmaf(eps_e, y0, gy0);
            gy1 = fmaf(eps_e, y1, gy1);
            gy2 = fmaf(eps_e, y2, gy2);
            gy3 = fmaf(eps_e, y3, gy3);

            const float* qm = Qm_s + f * 16;
            float ls = LSC[f];
#pragma unroll
            for (int l = 0; l < 4; l++) {
                float g2 = SCALE_C * (qm[0 * 4 + l] * gy0 + qm[1 * 4 + l] * gy1 +
                                      qm[2 * 4 + l] * gy2 + qm[3 * 4 + l] * gy3);
                float gcl = (l == 0) ? gc0 : (l == 1) ? gc1 : (l == 2) ? gc2 : gc3;
                buf[(l * F_ + f) * 64 + pxa] = ls * (gcl - g2);
            }
        }
        __syncthreads();

        // ---------- backward + update: x[c][px] -= (x - xn + W^T v)/denom ----------
        {
            unsigned long long bac[4][4];
#pragma unroll
            for (int k = 0; k < 4; k++)
#pragma unroll
                for (int j = 0; j < 4; j++) bac[k][j] = 0ull;

            const float* vcol = buf + px0;
#pragma unroll 2
            for (int gf = 0; gf < GF; gf += 2) {
                ulonglong2 v0a = *(const ulonglong2*)(vcol + gf * 64);
                ulonglong2 v1a = *(const ulonglong2*)(vcol + gf * 64 + 4);
                ulonglong2 v0b = *(const ulonglong2*)(vcol + (gf + 1) * 64);
                ulonglong2 v1b = *(const ulonglong2*)(vcol + (gf + 1) * 64 + 4);
#pragma unroll
                for (int k = 0; k < 4; k++) {
                    float2 w = *(const float2*)(&Wf_s[(cg + 32 * k) * WFS + gf]);
                    unsigned long long wpa = pack2(w.x, w.x);
                    unsigned long long wpb = pack2(w.y, w.y);
                    fma2(bac[k][0], wpa, v0a.x);
                    fma2(bac[k][1], wpa, v0a.y);
                    fma2(bac[k][2], wpa, v1a.x);
                    fma2(bac[k][3], wpa, v1a.y);
                    fma2(bac[k][0], wpb, v0b.x);
                    fma2(bac[k][1], wpb, v0b.y);
                    fma2(bac[k][2], wpb, v1b.x);
                    fma2(bac[k][3], wpb, v1b.y);
                }
            }
#pragma unroll
            for (int k = 0; k < 4; k++) {
                int c = cg + 32 * k;
                const float* xng = xnb + c * 16384 + px0;
                float4 n0 = *(const float4*)(xng);
                float4 n1 = *(const float4*)(xng + 4);
                float* xr = x_s + c * 64 + px0;
                float4 xo0 = *(float4*)(xr);
                float4 xo1 = *(float4*)(xr + 4);
                float2 a0 = unpack2(bac[k][0]);
                float2 a1 = unpack2(bac[k][1]);
                float2 a2 = unpack2(bac[k][2]);
                float2 a3 = unpack2(bac[k][3]);
                xo0.x = xo0.x - (xo0.x - n0.x + a0.x) * inv_denom;
                xo0.y = xo0.y - (xo0.y - n0.y + a0.y) * inv_denom;
                xo0.z = xo0.z - (xo0.z - n0.z + a1.x) * inv_denom;
                xo0.w = xo0.w - (xo0.w - n0.w + a1.y) * inv_denom;
                xo1.x = xo1.x - (xo1.x - n1.x + a2.x) * inv_denom;
                xo1.y = xo1.y - (xo1.y - n1.y + a2.y) * inv_denom;
                xo1.z = xo1.z - (xo1.z - n1.z + a3.x) * inv_denom;
                xo1.w = xo1.w - (xo1.w - n1.w + a3.y) * inv_denom;
                *(float4*)(xr) = xo0;
                *(float4*)(xr + 4) = xo1;
            }
        }
        __syncthreads();
    }

    for (int i = t; i < C_ * NPIX; i += THREADS) {
        int c = i >> 6, p = i & 63;
        outb[c * 16384 + p] = x_s[i];
    }
}

extern "C" void kernel_launch(void* const* d_in, const int* in_sizes, int n_in,
                              void* d_out, int out_size) {
    const float* xn    = (const float*)d_in[0];
    const float* sigma = (const float*)d_in[1];
    const float* Qp    = (const float*)d_in[2];
    const float* tausp = (const float*)d_in[3];
    const float* lamb  = (const float*)d_in[4];
    const float* epso  = (const float*)d_in[5];
    const float* w1    = (const float*)d_in[6];
    const float* b1    = (const float*)d_in[7];
    const float* w2    = (const float*)d_in[8];
    const float* b2    = (const float*)d_in[9];
    const float* w3    = (const float*)d_in[10];
    const float* b3    = (const float*)d_in[11];
    const float* Wf    = (const float*)d_in[12];
    const int* niter   = (const int*)d_in[13];
    float* out = (float*)d_out;

    cudaFuncSetAttribute(mfoe_kernel, cudaFuncAttributeMaxDynamicSharedMemorySize, SMEM_BYTES);
    precomp_kernel<<<1, 64>>>(sigma, Qp, tausp, lamb, epso, w1, b1, w2, b2, w3, b3);
    mfoe_kernel<<<512, THREADS, SMEM_BYTES>>>(xn, Wf, niter, out);
}